// round 1
// baseline (speedup 1.0000x reference)
#include <cuda_runtime.h>
#include <math.h>

// PixelContrastLoss: x_anchor [64,128,128] f32, y_anchor [64] i32 -> scalar f32
// N = 8192 rows, D = 128. loss_i = -log(P/(S+1e-8)+1e-8), mean over rows.
//   S_i = sum_j exp(sim_ij - 1), P_i = masked sum, mask(i,j) = (y[i>>7]==y[j&63])
// Row max of sim is exactly 1 (normalized features), so no max pass needed.

#define NTOT   8192
#define DIM    128
#define TILE   128
#define JSPLIT 8
#define JT_PER 8      // (NTOT/TILE)/JSPLIT = 64/8
#define PAD    129    // smem row stride in floats (bank-conflict mitigation)

__device__ float g_feat[NTOT * DIM];
__device__ float g_partS[JSPLIT * NTOT];
__device__ float g_partP[JSPLIT * NTOT];

// ---------------------------------------------------------------------------
// 1) L2-normalize rows: one warp per row, float4 loads, shuffle reduce.
// ---------------------------------------------------------------------------
__global__ void knorm(const float* __restrict__ x) {
    int row  = blockIdx.x * 4 + threadIdx.y;   // 4 warps / block
    int lane = threadIdx.x;
    float4 v = ((const float4*)(x + (size_t)row * DIM))[lane];
    float s = v.x * v.x + v.y * v.y + v.z * v.z + v.w * v.w;
    #pragma unroll
    for (int o = 16; o; o >>= 1) s += __shfl_xor_sync(0xffffffffu, s, o);
    float inv = 1.0f / fmaxf(sqrtf(s), 1e-12f);
    float4 o4 = make_float4(v.x * inv, v.y * inv, v.z * inv, v.w * inv);
    ((float4*)(g_feat + (size_t)row * DIM))[lane] = o4;
}

// ---------------------------------------------------------------------------
// 2) Main: 128x128 tile GEMM (C = A * B^T over D=128) fused with exp + masked
//    row reductions. Grid (64 row-tiles, JSPLIT). 256 thr, 8x8 micro-tile.
//    Partials written disjointly -> fully deterministic, no atomics.
// ---------------------------------------------------------------------------
__global__ __launch_bounds__(256, 1) void kmain(const int* __restrict__ y) {
    extern __shared__ float sm[];
    float* As = sm;                // [TILE][PAD]
    float* Bs = sm + TILE * PAD;   // [TILE][PAD]

    const int tid = threadIdx.x;
    const int tx  = tid & 15;
    const int ty  = tid >> 4;
    const int bx  = blockIdx.x;    // row tile (0..63)
    const int by  = blockIdx.y;    // j-split  (0..JSPLIT-1)
    const int i0  = bx * TILE;

    // Load A tile once (coalesced float4 gmem reads, scalar smem writes).
    #pragma unroll
    for (int it = 0; it < 16; ++it) {
        int r  = it * 8 + (tid >> 5);
        int k4 = (tid & 31) * 4;
        float4 v = *(const float4*)(g_feat + (size_t)(i0 + r) * DIM + k4);
        float* d = As + r * PAD + k4;
        d[0] = v.x; d[1] = v.y; d[2] = v.z; d[3] = v.w;
    }

    // Row label constant over the whole tile: y[(i0+r)>>7] == y[bx].
    const int rlab = y[bx];
    // Column label periodic-64 and identical for every j tile: y[jj & 63].
    // Columns jj and jj+64 share the same mask bit -> 4 bools per thread.
    bool m[4];
    #pragma unroll
    for (int c = 0; c < 4; ++c) m[c] = (y[(tx * 4 + c) & 63] == rlab);

    float rowS[8], rowP[8];
    #pragma unroll
    for (int r = 0; r < 8; ++r) { rowS[r] = 0.f; rowP[r] = 0.f; }

    for (int jt = 0; jt < JT_PER; ++jt) {
        const int j0 = (by * JT_PER + jt) * TILE;

        __syncthreads();   // protect Bs from previous iteration's readers
        #pragma unroll
        for (int it = 0; it < 16; ++it) {
            int r  = it * 8 + (tid >> 5);
            int k4 = (tid & 31) * 4;
            float4 v = *(const float4*)(g_feat + (size_t)(j0 + r) * DIM + k4);
            float* d = Bs + r * PAD + k4;
            d[0] = v.x; d[1] = v.y; d[2] = v.z; d[3] = v.w;
        }
        __syncthreads();

        float acc[8][8];
        #pragma unroll
        for (int ri = 0; ri < 8; ++ri)
            #pragma unroll
            for (int ci = 0; ci < 8; ++ci) acc[ri][ci] = 0.f;

        #pragma unroll 8
        for (int k = 0; k < DIM; ++k) {
            float a[8], b[8];
            #pragma unroll
            for (int r = 0; r < 4; ++r) {
                a[r]     = As[(ty * 4 + r) * PAD + k];
                a[r + 4] = As[(64 + ty * 4 + r) * PAD + k];
                b[r]     = Bs[(tx * 4 + r) * PAD + k];
                b[r + 4] = Bs[(64 + tx * 4 + r) * PAD + k];
            }
            #pragma unroll
            for (int ri = 0; ri < 8; ++ri)
                #pragma unroll
                for (int ci = 0; ci < 8; ++ci)
                    acc[ri][ci] = fmaf(a[ri], b[ci], acc[ri][ci]);
        }

        // Fused epilogue: exp(sim - 1), split by mask, accumulate per row.
        #pragma unroll
        for (int ri = 0; ri < 8; ++ri) {
            float s = 0.f, p = 0.f;
            #pragma unroll
            for (int ci = 0; ci < 8; ++ci) {
                float e = __expf(acc[ri][ci] - 1.0f);
                s += e;
                if (m[ci & 3]) p += e;
            }
            rowS[ri] += s; rowP[ri] += p;
        }
    }

    // Reduce across the 16 tx lanes (two independent 16-lane halves per warp).
    #pragma unroll
    for (int ri = 0; ri < 8; ++ri) {
        #pragma unroll
        for (int o = 8; o; o >>= 1) {
            rowS[ri] += __shfl_xor_sync(0xffffffffu, rowS[ri], o);
            rowP[ri] += __shfl_xor_sync(0xffffffffu, rowP[ri], o);
        }
    }
    if (tx == 0) {
        #pragma unroll
        for (int ri = 0; ri < 8; ++ri) {
            int lrow = (ri < 4) ? (ty * 4 + ri) : (64 + ty * 4 + (ri - 4));
            int grow = i0 + lrow;
            g_partS[by * NTOT + grow] = rowS[ri];
            g_partP[by * NTOT + grow] = rowP[ri];
        }
    }
}

// ---------------------------------------------------------------------------
// 3) Final: fold JSPLIT partials per row, per-row loss, mean.
// ---------------------------------------------------------------------------
__global__ void kfinal(float* __restrict__ out) {
    __shared__ float red[256];
    int tid = threadIdx.x;
    float acc = 0.f;
    for (int row = tid; row < NTOT; row += 256) {
        float S = 0.f, P = 0.f;
        #pragma unroll
        for (int s = 0; s < JSPLIT; ++s) {
            S += g_partS[s * NTOT + row];
            P += g_partP[s * NTOT + row];
        }
        acc += -logf(P / (S + 1e-8f) + 1e-8f);
    }
    red[tid] = acc;
    __syncthreads();
    #pragma unroll
    for (int o = 128; o; o >>= 1) {
        if (tid < o) red[tid] += red[tid + o];
        __syncthreads();
    }
    if (tid == 0) out[0] = red[0] / (float)NTOT;
}

// ---------------------------------------------------------------------------
extern "C" void kernel_launch(void* const* d_in, const int* in_sizes, int n_in,
                              void* d_out, int out_size) {
    const float* x = (const float*)d_in[0];   // [64,128,128] f32
    const int*   y = (const int*)d_in[1];     // [64] i32
    float*     out = (float*)d_out;

    knorm<<<NTOT / 4, dim3(32, 4)>>>(x);

    size_t smem = (size_t)2 * TILE * PAD * sizeof(float);  // 132096 B
    cudaFuncSetAttribute(kmain, cudaFuncAttributeMaxDynamicSharedMemorySize,
                         (int)smem);
    kmain<<<dim3(NTOT / TILE, JSPLIT), 256, smem>>>(y);

    kfinal<<<1, 256>>>(out);
}

// round 6
// speedup vs baseline: 2.9413x; 2.9413x over previous
#include <cuda_runtime.h>
#include <cuda_bf16.h>
#include <math.h>
#include <stdint.h>

// PixelContrastLoss via warp-level bf16 tensor cores (mma.sync m16n8k16).
// tcgen05 is unavailable: harness builds PTX at .target sm_103 (no 'a'),
// which gates off all arch-accelerated (tcgen05/TMEM) instructions.
// x [64,128,128] f32, y [64] i32 -> scalar f32.
// N=8192 rows, D=128. loss_i = -log(P/(S+1e-8)+1e-8), mean over rows;
// S_i = sum_j exp(sim_ij - 1) (row max == 1 exactly for normalized rows),
// P_i = masked sum, mask(i,j) = (y[i>>7] == y[j&63]) (period-64 in j).

#define NTOT    8192
#define DIM     128
#define TM      128
#define TN      128
#define JSPLIT  16
#define TILES_PER 4          // (NTOT/JSPLIT)/TN
#define THREADS 256
#define NSLOT   64           // JSPLIT * 4 warp_n columns

__device__ __align__(16) __nv_bfloat16 g_feat[NTOT * DIM];
__device__ float g_partS[NSLOT * NTOT];
__device__ float g_partP[NSLOT * NTOT];

// smem: A tile 32KB + B double buffer 2x32KB
#define SA   0
#define SB0  32768
#define SB1  65536
#define SMEM_TOTAL 98304

__device__ __forceinline__ uint32_t smem_u32(const void* p) {
    uint32_t a;
    asm("{ .reg .u64 t; cvta.to.shared.u64 t, %1; cvt.u32.u64 %0, t; }"
        : "=r"(a) : "l"(p));
    return a;
}
__device__ __forceinline__ void ldsm_x4(uint32_t r[4], uint32_t addr) {
    asm volatile("ldmatrix.sync.aligned.m8n8.x4.shared.b16 {%0,%1,%2,%3}, [%4];"
                 : "=r"(r[0]), "=r"(r[1]), "=r"(r[2]), "=r"(r[3]) : "r"(addr));
}
__device__ __forceinline__ void mma16816(float d[4], const uint32_t a[4],
                                         const uint32_t* b) {
    asm volatile(
        "mma.sync.aligned.m16n8k16.row.col.f32.bf16.bf16.f32 "
        "{%0,%1,%2,%3}, {%4,%5,%6,%7}, {%8,%9}, {%0,%1,%2,%3};"
        : "+f"(d[0]), "+f"(d[1]), "+f"(d[2]), "+f"(d[3])
        : "r"(a[0]), "r"(a[1]), "r"(a[2]), "r"(a[3]), "r"(b[0]), "r"(b[1]));
}
#define CP_COMMIT() asm volatile("cp.async.commit_group;" ::: "memory")
#define CP_WAIT0()  asm volatile("cp.async.wait_group 0;" ::: "memory")

// Load a 128x128 bf16 tile into swizzled smem via cp.async.
// Row = 256B = 16 chunks of 16B; swizzle: chunk' = chunk ^ (row & 7).
__device__ __forceinline__ void cpa_tile(uint32_t dst, int row0, int tid) {
    #pragma unroll
    for (int it = 0; it < 8; ++it) {
        int i = it * THREADS + tid;
        int r = i >> 4, c = i & 15;
        const void* src =
            (const char*)g_feat + ((size_t)(row0 + r) * DIM + c * 8) * 2;
        uint32_t d = dst + r * 256 + ((c ^ (r & 7)) << 4);
        asm volatile("cp.async.cg.shared.global [%0], [%1], 16;"
                     :: "r"(d), "l"(src));
    }
}

// ---------------------------------------------------------------------------
// 1) L2-normalize + bf16 convert: one warp per row.
// ---------------------------------------------------------------------------
__global__ void knorm(const float* __restrict__ x) {
    int row  = blockIdx.x * 8 + (threadIdx.x >> 5);
    int lane = threadIdx.x & 31;
    float4 v = ((const float4*)(x + (size_t)row * DIM))[lane];
    float s = v.x * v.x + v.y * v.y + v.z * v.z + v.w * v.w;
    #pragma unroll
    for (int o = 16; o; o >>= 1) s += __shfl_xor_sync(0xffffffffu, s, o);
    float inv = 1.0f / fmaxf(sqrtf(s), 1e-12f);
    __nv_bfloat162 p0 = __floats2bfloat162_rn(v.x * inv, v.y * inv);
    __nv_bfloat162 p1 = __floats2bfloat162_rn(v.z * inv, v.w * inv);
    uint2 o2;
    o2.x = *(uint32_t*)&p0; o2.y = *(uint32_t*)&p1;
    ((uint2*)(g_feat + (size_t)row * DIM))[lane] = o2;
}

// ---------------------------------------------------------------------------
// 2) main: 128x128 CTA tile, 8 warps (2x4), warp tile 64x32, K=128.
//    cp.async double-buffered B; epilogue (exp + masked sums) from registers.
// ---------------------------------------------------------------------------
__global__ __launch_bounds__(THREADS, 1) void kmain(const int* __restrict__ y) {
    extern __shared__ char smem[];
    const uint32_t sb = smem_u32(smem);
    const int tid = threadIdx.x;
    const int wid = tid >> 5, l = tid & 31;
    const int warp_m = wid >> 2, warp_n = wid & 3;
    const int bx = blockIdx.x, by = blockIdx.y;
    const int i0 = bx * TM;
    const int col0 = by * (NTOT / JSPLIT);

    // mask bits: bit(nf*2+par) = (y[col mod 64] == y[bx])
    const int rlab = y[bx];
    uint32_t mbits = 0;
    #pragma unroll
    for (int nf = 0; nf < 4; ++nf)
        #pragma unroll
        for (int par = 0; par < 2; ++par) {
            int c = (warp_n & 1) * 32 + nf * 8 + 2 * (l & 3) + par;
            if (y[c] == rlab) mbits |= 1u << (nf * 2 + par);
        }

    // prologue: A + B tile 0
    cpa_tile(sb + SA, i0, tid);
    cpa_tile(sb + SB0, col0, tid);
    CP_COMMIT();
    CP_WAIT0();
    __syncthreads();

    // ldmatrix lane geometry
    const int mat = l >> 3, lrow = l & 7;
    // A: matrices ordered (m0-7,k0-7)(m8-15,k0-7)(m0-7,k8-15)(m8-15,k8-15)
    uint32_t a_rb[4]; int a_rx[4];
    #pragma unroll
    for (int mf = 0; mf < 4; ++mf) {
        int r = warp_m * 64 + mf * 16 + ((mat & 1) << 3) + lrow;
        a_rb[mf] = sb + SA + r * 256;
        a_rx[mf] = r & 7;
    }
    const int a_kh = mat >> 1;
    // B: matrices ordered (n0-7,k0-7)(n0-7,k8-15)(n8-15,k0-7)(n8-15,k8-15)
    uint32_t b_off[2]; int b_rx[2];
    #pragma unroll
    for (int p = 0; p < 2; ++p) {
        int n = warp_n * 32 + p * 16 + ((mat >> 1) << 3) + lrow;
        b_off[p] = n * 256;
        b_rx[p] = n & 7;
    }
    const int b_kh = mat & 1;

    float acc[4][4][4];
    #pragma unroll
    for (int mf = 0; mf < 4; ++mf)
        #pragma unroll
        for (int nf = 0; nf < 4; ++nf)
            #pragma unroll
            for (int d = 0; d < 4; ++d) acc[mf][nf][d] = 0.f;
    float rowS[8], rowP[8];
    #pragma unroll
    for (int r = 0; r < 8; ++r) { rowS[r] = 0.f; rowP[r] = 0.f; }

    for (int jt = 0; jt < TILES_PER; ++jt) {
        const uint32_t sbB = sb + ((jt & 1) ? SB1 : SB0);
        if (jt + 1 < TILES_PER) {
            cpa_tile(sb + ((jt & 1) ? SB0 : SB1), col0 + (jt + 1) * TN, tid);
            CP_COMMIT();
        }

        #pragma unroll
        for (int k = 0; k < 8; ++k) {
            uint32_t af[4][4], bf[2][4];
            #pragma unroll
            for (int mf = 0; mf < 4; ++mf)
                ldsm_x4(af[mf],
                        a_rb[mf] + ((((k << 1) + a_kh) ^ a_rx[mf]) << 4));
            #pragma unroll
            for (int p = 0; p < 2; ++p)
                ldsm_x4(bf[p], sbB + b_off[p] +
                                   ((((k << 1) + b_kh) ^ b_rx[p]) << 4));
            #pragma unroll
            for (int mf = 0; mf < 4; ++mf)
                #pragma unroll
                for (int nf = 0; nf < 4; ++nf)
                    mma16816(acc[mf][nf], af[mf], &bf[nf >> 1][(nf & 1) * 2]);
        }

        // epilogue from registers: d0=(lo,par0) d1=(lo,par1) d2=(hi,par0) d3=(hi,par1)
        #pragma unroll
        for (int mf = 0; mf < 4; ++mf)
            #pragma unroll
            for (int nf = 0; nf < 4; ++nf) {
                float e0 = __expf(acc[mf][nf][0] - 1.0f);
                float e1 = __expf(acc[mf][nf][1] - 1.0f);
                float e2 = __expf(acc[mf][nf][2] - 1.0f);
                float e3 = __expf(acc[mf][nf][3] - 1.0f);
                rowS[mf * 2 + 0] += e0 + e1;
                rowS[mf * 2 + 1] += e2 + e3;
                if ((mbits >> (nf * 2 + 0)) & 1) {
                    rowP[mf * 2 + 0] += e0; rowP[mf * 2 + 1] += e2;
                }
                if ((mbits >> (nf * 2 + 1)) & 1) {
                    rowP[mf * 2 + 0] += e1; rowP[mf * 2 + 1] += e3;
                }
                acc[mf][nf][0] = 0.f; acc[mf][nf][1] = 0.f;
                acc[mf][nf][2] = 0.f; acc[mf][nf][3] = 0.f;
            }

        if (jt + 1 < TILES_PER) CP_WAIT0();
        __syncthreads();
    }

    // reduce over the 4 lanes of each quad (same row), write disjoint partials
    #pragma unroll
    for (int idx = 0; idx < 8; ++idx) {
        rowS[idx] += __shfl_xor_sync(0xffffffffu, rowS[idx], 1);
        rowS[idx] += __shfl_xor_sync(0xffffffffu, rowS[idx], 2);
        rowP[idx] += __shfl_xor_sync(0xffffffffu, rowP[idx], 1);
        rowP[idx] += __shfl_xor_sync(0xffffffffu, rowP[idx], 2);
    }
    if ((l & 3) == 0) {
        const int slot = by * 4 + warp_n;
        #pragma unroll
        for (int idx = 0; idx < 8; ++idx) {
            int row = i0 + warp_m * 64 + (idx >> 1) * 16 + (l >> 2) +
                      (idx & 1) * 8;
            g_partS[slot * NTOT + row] = rowS[idx];
            g_partP[slot * NTOT + row] = rowP[idx];
        }
    }
}

// ---------------------------------------------------------------------------
// 3) final: fold 64 partial slots, per-row loss, mean.
// ---------------------------------------------------------------------------
__global__ void kfinal(float* __restrict__ out) {
    __shared__ float red[256];
    int tid = threadIdx.x;
    float acc = 0.f;
    for (int row = tid; row < NTOT; row += 256) {
        float S = 0.f, P = 0.f;
        #pragma unroll
        for (int s = 0; s < NSLOT; ++s) {
            S += g_partS[s * NTOT + row];
            P += g_partP[s * NTOT + row];
        }
        acc += -logf(P / (S + 1e-8f) + 1e-8f);
    }
    red[tid] = acc;
    __syncthreads();
    #pragma unroll
    for (int o = 128; o; o >>= 1) {
        if (tid < o) red[tid] += red[tid + o];
        __syncthreads();
    }
    if (tid == 0) out[0] = red[0] / (float)NTOT;
}

// ---------------------------------------------------------------------------
extern "C" void kernel_launch(void* const* d_in, const int* in_sizes, int n_in,
                              void* d_out, int out_size) {
    const float* x = (const float*)d_in[0];
    const int*   y = (const int*)d_in[1];
    float*     out = (float*)d_out;

    knorm<<<NTOT / 8, THREADS>>>(x);

    cudaFuncSetAttribute(kmain, cudaFuncAttributeMaxDynamicSharedMemorySize,
                         SMEM_TOTAL);
    kmain<<<dim3(NTOT / TM, JSPLIT), THREADS, SMEM_TOTAL>>>(y);

    kfinal<<<1, 256>>>(out);
}

// round 10
// speedup vs baseline: 6.6667x; 2.2666x over previous
#include <cuda_runtime.h>
#include <cuda_bf16.h>
#include <math.h>
#include <stdint.h>

// PixelContrastLoss via warp-level bf16 tensor cores (mma.sync m16n8k16).
// tcgen05 unavailable (harness builds .target sm_103, no 'a' suffix).
// x [64,128,128] f32, y [64] i32 -> scalar f32.
// N=8192 rows, D=128. loss_i = -log(P/(S+1e-8)+1e-8), mean over rows;
// S_i = sum_j exp(sim_ij - 1) (row max == 1 exactly), P_i masked sum,
// mask(i,j) = (y[i>>7] == y[j&63]) (period-64 in j).
//
// R7: occupancy fix. 512 thr / 16 warps (4 per SMSP), warp tile 32x32,
// cross-warp_n smem reduction (64 -> 16 partial slots), 2-stage final.

#define NTOT    8192
#define DIM     128
#define TM      128
#define TN      128
#define JSPLIT  16
#define TILES_PER 4          // (NTOT/JSPLIT)/TN
#define THREADS 512
#define NSLOT   16           // JSPLIT slots after in-CTA warp_n reduction

__device__ __align__(16) __nv_bfloat16 g_feat[NTOT * DIM];
__device__ float g_partS[NSLOT * NTOT];
__device__ float g_partP[NSLOT * NTOT];
__device__ float g_red[64];

// smem: A tile 32KB + B double buffer 2x32KB (reused as reduce buffer at end)
#define SA   0
#define SB0  32768
#define SB1  65536
#define SMEM_TOTAL 98304

__device__ __forceinline__ uint32_t smem_u32(const void* p) {
    uint32_t a;
    asm("{ .reg .u64 t; cvta.to.shared.u64 t, %1; cvt.u32.u64 %0, t; }"
        : "=r"(a) : "l"(p));
    return a;
}
__device__ __forceinline__ void ldsm_x4(uint32_t r[4], uint32_t addr) {
    asm volatile("ldmatrix.sync.aligned.m8n8.x4.shared.b16 {%0,%1,%2,%3}, [%4];"
                 : "=r"(r[0]), "=r"(r[1]), "=r"(r[2]), "=r"(r[3]) : "r"(addr));
}
__device__ __forceinline__ void mma16816(float d[4], const uint32_t a[4],
                                         const uint32_t* b) {
    asm volatile(
        "mma.sync.aligned.m16n8k16.row.col.f32.bf16.bf16.f32 "
        "{%0,%1,%2,%3}, {%4,%5,%6,%7}, {%8,%9}, {%0,%1,%2,%3};"
        : "+f"(d[0]), "+f"(d[1]), "+f"(d[2]), "+f"(d[3])
        : "r"(a[0]), "r"(a[1]), "r"(a[2]), "r"(a[3]), "r"(b[0]), "r"(b[1]));
}
#define CP_COMMIT() asm volatile("cp.async.commit_group;" ::: "memory")
#define CP_WAIT0()  asm volatile("cp.async.wait_group 0;" ::: "memory")

// Load a 128x128 bf16 tile into swizzled smem via cp.async.
// Row = 256B = 16 chunks of 16B; swizzle: chunk' = chunk ^ (row & 7).
__device__ __forceinline__ void cpa_tile(uint32_t dst, int row0, int tid) {
    #pragma unroll
    for (int it = 0; it < 4; ++it) {
        int i = it * THREADS + tid;
        int r = i >> 4, c = i & 15;
        const void* src =
            (const char*)g_feat + ((size_t)(row0 + r) * DIM + c * 8) * 2;
        uint32_t d = dst + r * 256 + ((c ^ (r & 7)) << 4);
        asm volatile("cp.async.cg.shared.global [%0], [%1], 16;"
                     :: "r"(d), "l"(src));
    }
}

// ---------------------------------------------------------------------------
// 1) L2-normalize + bf16 convert: one warp per row.
// ---------------------------------------------------------------------------
__global__ void knorm(const float* __restrict__ x) {
    int row  = blockIdx.x * 8 + (threadIdx.x >> 5);
    int lane = threadIdx.x & 31;
    float4 v = ((const float4*)(x + (size_t)row * DIM))[lane];
    float s = v.x * v.x + v.y * v.y + v.z * v.z + v.w * v.w;
    #pragma unroll
    for (int o = 16; o; o >>= 1) s += __shfl_xor_sync(0xffffffffu, s, o);
    float inv = 1.0f / fmaxf(sqrtf(s), 1e-12f);
    __nv_bfloat162 p0 = __floats2bfloat162_rn(v.x * inv, v.y * inv);
    __nv_bfloat162 p1 = __floats2bfloat162_rn(v.z * inv, v.w * inv);
    uint2 o2;
    o2.x = *(uint32_t*)&p0; o2.y = *(uint32_t*)&p1;
    ((uint2*)(g_feat + (size_t)row * DIM))[lane] = o2;
}

// ---------------------------------------------------------------------------
// 2) main: 128x128 CTA tile, 16 warps (4x4), warp tile 32x32, K=128.
//    cp.async double-buffered B; epilogue (exp + masked sums) from registers.
// ---------------------------------------------------------------------------
__global__ __launch_bounds__(THREADS, 1) void kmain(const int* __restrict__ y) {
    extern __shared__ char smem[];
    const uint32_t sb = smem_u32(smem);
    const int tid = threadIdx.x;
    const int wid = tid >> 5, l = tid & 31;
    const int warp_m = wid >> 2, warp_n = wid & 3;
    const int bx = blockIdx.x, by = blockIdx.y;
    const int i0 = bx * TM;
    const int col0 = by * (NTOT / JSPLIT);

    // mask bits: bit(nf*2+par) = (y[col mod 64] == y[bx])
    const int rlab = y[bx];
    uint32_t mbits = 0;
    #pragma unroll
    for (int nf = 0; nf < 4; ++nf)
        #pragma unroll
        for (int par = 0; par < 2; ++par) {
            int c = (warp_n & 1) * 32 + nf * 8 + 2 * (l & 3) + par;
            if (y[c] == rlab) mbits |= 1u << (nf * 2 + par);
        }

    // prologue: A + B tile 0
    cpa_tile(sb + SA, i0, tid);
    cpa_tile(sb + SB0, col0, tid);
    CP_COMMIT();
    CP_WAIT0();
    __syncthreads();

    // ldmatrix lane geometry
    const int mat = l >> 3, lrow = l & 7;
    // A: matrices (m0-7,k0-7)(m8-15,k0-7)(m0-7,k8-15)(m8-15,k8-15)
    uint32_t a_rb[2]; int a_rx[2];
    #pragma unroll
    for (int mf = 0; mf < 2; ++mf) {
        int r = warp_m * 32 + mf * 16 + ((mat & 1) << 3) + lrow;
        a_rb[mf] = sb + SA + r * 256;
        a_rx[mf] = r & 7;
    }
    const int a_kh = mat >> 1;
    // B: matrices (n0-7,k0-7)(n0-7,k8-15)(n8-15,k0-7)(n8-15,k8-15)
    uint32_t b_off[2]; int b_rx[2];
    #pragma unroll
    for (int p = 0; p < 2; ++p) {
        int n = warp_n * 32 + p * 16 + ((mat >> 1) << 3) + lrow;
        b_off[p] = n * 256;
        b_rx[p] = n & 7;
    }
    const int b_kh = mat & 1;

    float acc[2][4][4];
    #pragma unroll
    for (int mf = 0; mf < 2; ++mf)
        #pragma unroll
        for (int nf = 0; nf < 4; ++nf)
            #pragma unroll
            for (int d = 0; d < 4; ++d) acc[mf][nf][d] = 0.f;
    float rowS[4], rowP[4];
    #pragma unroll
    for (int r = 0; r < 4; ++r) { rowS[r] = 0.f; rowP[r] = 0.f; }

    for (int jt = 0; jt < TILES_PER; ++jt) {
        const uint32_t sbB = sb + ((jt & 1) ? SB1 : SB0);
        if (jt + 1 < TILES_PER) {
            cpa_tile(sb + ((jt & 1) ? SB0 : SB1), col0 + (jt + 1) * TN, tid);
            CP_COMMIT();
        }

        #pragma unroll
        for (int k = 0; k < 8; ++k) {
            uint32_t af[2][4], bf[2][4];
            #pragma unroll
            for (int p = 0; p < 2; ++p)
                ldsm_x4(bf[p], sbB + b_off[p] +
                                   ((((k << 1) + b_kh) ^ b_rx[p]) << 4));
            #pragma unroll
            for (int mf = 0; mf < 2; ++mf)
                ldsm_x4(af[mf],
                        a_rb[mf] + ((((k << 1) + a_kh) ^ a_rx[mf]) << 4));
            #pragma unroll
            for (int mf = 0; mf < 2; ++mf)
                #pragma unroll
                for (int nf = 0; nf < 4; ++nf)
                    mma16816(acc[mf][nf], af[mf], &bf[nf >> 1][(nf & 1) * 2]);
        }

        // epilogue: d0=(lo,par0) d1=(lo,par1) d2=(hi,par0) d3=(hi,par1)
        #pragma unroll
        for (int mf = 0; mf < 2; ++mf)
            #pragma unroll
            for (int nf = 0; nf < 4; ++nf) {
                float e0 = __expf(acc[mf][nf][0] - 1.0f);
                float e1 = __expf(acc[mf][nf][1] - 1.0f);
                float e2 = __expf(acc[mf][nf][2] - 1.0f);
                float e3 = __expf(acc[mf][nf][3] - 1.0f);
                rowS[mf * 2 + 0] += e0 + e1;
                rowS[mf * 2 + 1] += e2 + e3;
                if ((mbits >> (nf * 2 + 0)) & 1) {
                    rowP[mf * 2 + 0] += e0; rowP[mf * 2 + 1] += e2;
                }
                if ((mbits >> (nf * 2 + 1)) & 1) {
                    rowP[mf * 2 + 0] += e1; rowP[mf * 2 + 1] += e3;
                }
                acc[mf][nf][0] = 0.f; acc[mf][nf][1] = 0.f;
                acc[mf][nf][2] = 0.f; acc[mf][nf][3] = 0.f;
            }

        if (jt + 1 < TILES_PER) CP_WAIT0();
        __syncthreads();
    }

    // quad reduce (lanes of a quad share the same rows)
    #pragma unroll
    for (int idx = 0; idx < 4; ++idx) {
        rowS[idx] += __shfl_xor_sync(0xffffffffu, rowS[idx], 1);
        rowS[idx] += __shfl_xor_sync(0xffffffffu, rowS[idx], 2);
        rowP[idx] += __shfl_xor_sync(0xffffffffu, rowP[idx], 1);
        rowP[idx] += __shfl_xor_sync(0xffffffffu, rowP[idx], 2);
    }

    // cross-warp_n reduction via smem (reuse tile buffers; MMAs are done)
    float* red = (float*)smem;      // [4 warp_n][128 rows][2]
    __syncthreads();
    if ((l & 3) == 0) {
        #pragma unroll
        for (int idx = 0; idx < 4; ++idx) {
            int row_local = warp_m * 32 + (idx >> 1) * 16 + (l >> 2) +
                            (idx & 1) * 8;
            red[(warp_n * 128 + row_local) * 2 + 0] = rowS[idx];
            red[(warp_n * 128 + row_local) * 2 + 1] = rowP[idx];
        }
    }
    __syncthreads();
    if (tid < 128) {
        float S = 0.f, P = 0.f;
        #pragma unroll
        for (int wn = 0; wn < 4; ++wn) {
            S += red[(wn * 128 + tid) * 2 + 0];
            P += red[(wn * 128 + tid) * 2 + 1];
        }
        g_partS[by * NTOT + i0 + tid] = S;
        g_partP[by * NTOT + i0 + tid] = P;
    }
}

// ---------------------------------------------------------------------------
// 3a) stage 1: 64 blocks x 128 rows -> per-block loss partial.
// ---------------------------------------------------------------------------
__global__ void kfinal1() {
    __shared__ float red[4];
    int tid = threadIdx.x;
    int row = blockIdx.x * 128 + tid;
    float S = 0.f, P = 0.f;
    #pragma unroll
    for (int s = 0; s < NSLOT; ++s) {
        S += g_partS[s * NTOT + row];
        P += g_partP[s * NTOT + row];
    }
    float acc = -logf(P / (S + 1e-8f) + 1e-8f);
    #pragma unroll
    for (int o = 16; o; o >>= 1) acc += __shfl_xor_sync(0xffffffffu, acc, o);
    if ((tid & 31) == 0) red[tid >> 5] = acc;
    __syncthreads();
    if (tid == 0)
        g_red[blockIdx.x] = red[0] + red[1] + red[2] + red[3];
}

// 3b) stage 2: fold 64 block partials, mean.
__global__ void kfinal2(float* __restrict__ out) {
    int tid = threadIdx.x;   // 64 threads
    float v = g_red[tid];
    #pragma unroll
    for (int o = 16; o; o >>= 1) v += __shfl_xor_sync(0xffffffffu, v, o);
    __shared__ float r[2];
    if ((tid & 31) == 0) r[tid >> 5] = v;
    __syncthreads();
    if (tid == 0) out[0] = (r[0] + r[1]) / (float)NTOT;
}

// ---------------------------------------------------------------------------
extern "C" void kernel_launch(void* const* d_in, const int* in_sizes, int n_in,
                              void* d_out, int out_size) {
    const float* x = (const float*)d_in[0];
    const int*   y = (const int*)d_in[1];
    float*     out = (float*)d_out;

    knorm<<<NTOT / 8, 256>>>(x);

    cudaFuncSetAttribute(kmain, cudaFuncAttributeMaxDynamicSharedMemorySize,
                         SMEM_TOTAL);
    kmain<<<dim3(NTOT / TM, JSPLIT), THREADS, SMEM_TOTAL>>>(y);

    kfinal1<<<64, 128>>>();
    kfinal2<<<1, 64>>>(out);
}